// round 4
// baseline (speedup 1.0000x reference)
#include <cuda_runtime.h>
#include <math.h>
#include <stdint.h>

// B=4,H=16 -> BH=64; S=1024; D=64; rel-pos P=32
#define BH   64
#define SEQ  1024
#define DH   64
#define NTHR 256
#define ISD  0.125f
#define NEGINF (-INFINITY)

// smem layout (bytes)
#define KS_STRIDE 68
#define VS_STRIDE 72
#define PS_STRIDE 132
#define OFF_KS   0                          // K tile [128][68] tf32 bits
#define OFF_VS   34816                      // V tile [128][72] tf32 bits
#define OFF_PS   71680                      // e tile tf32 [128][132] (also Q staging)
#define OFF_QPE  139264                     // qpe [128][34] f32
#define OFF_W    156672                     // tap e-values [128][34] f32
#define OFF_PEK  174080                     // pe_k [33][66] f32
#define OFF_PEV  182792
#define OFF_M    191504                     // M bound per row [128]
#define OFF_LR   192528                     // l partials [128][2]
#define OFF_WR   193552                     // w0 partials [128][2]
#define OFF_INV  194576                     // 1/l per row [128]
#define SMEM_TOTAL 195088

__device__ float g_maxk[BH];

static __device__ __forceinline__ uint32_t f2tf(float x) {
    uint32_t r; asm("cvt.rna.tf32.f32 %0, %1;" : "=r"(r) : "f"(x)); return r;
}
static __device__ __forceinline__ void mma8(float* d, const uint32_t* a,
                                            uint32_t b0, uint32_t b1) {
    asm volatile("mma.sync.aligned.m16n8k8.row.col.f32.tf32.tf32.f32 "
        "{%0,%1,%2,%3},{%4,%5,%6,%7},{%8,%9},{%0,%1,%2,%3};"
        : "+f"(d[0]), "+f"(d[1]), "+f"(d[2]), "+f"(d[3])
        : "r"(a[0]), "r"(a[1]), "r"(a[2]), "r"(a[3]), "r"(b0), "r"(b1));
}

// ---- precompute: per-bh max ||k_row|| ----
__global__ __launch_bounds__(256, 4)
void knorm_kernel(const float* __restrict__ K)
{
    __shared__ float red[8];
    const int bh = blockIdx.x, tid = threadIdx.x;
    const float* Kb = K + (size_t)bh * SEQ * DH;
    float mx = 0.f;
    for (int r = tid; r < SEQ; r += 256) {
        const float4* kr = (const float4*)(Kb + (size_t)r * DH);
        float s = 0.f;
        #pragma unroll
        for (int i = 0; i < 16; i++) {
            float4 v = kr[i];
            s += v.x*v.x + v.y*v.y + v.z*v.z + v.w*v.w;
        }
        mx = fmaxf(mx, s);
    }
    #pragma unroll
    for (int o = 16; o > 0; o >>= 1) mx = fmaxf(mx, __shfl_xor_sync(0xffffffffu, mx, o));
    if ((tid & 31) == 0) red[tid >> 5] = mx;
    __syncthreads();
    if (tid == 0) {
        float m = red[0];
        #pragma unroll
        for (int i = 1; i < 8; i++) m = fmaxf(m, red[i]);
        g_maxk[bh] = sqrtf(m);
    }
}

__global__ __launch_bounds__(NTHR, 1)
void relattn_mma(const float* __restrict__ Q, const float* __restrict__ K,
                 const float* __restrict__ V, const float* __restrict__ PEK,
                 const float* __restrict__ PEV,
                 float* __restrict__ Out, float* __restrict__ Pout)
{
    extern __shared__ char sm8[];
    uint32_t* ksu = (uint32_t*)(sm8 + OFF_KS);
    uint32_t* vsu = (uint32_t*)(sm8 + OFF_VS);
    float*    sPS = (float*)(sm8 + OFF_PS);
    uint32_t* psu = (uint32_t*)(sm8 + OFF_PS);
    float*    sQPE= (float*)(sm8 + OFF_QPE);
    float*    sW  = (float*)(sm8 + OFF_W);
    float*    sPEK= (float*)(sm8 + OFF_PEK);
    float*    sPEV= (float*)(sm8 + OFF_PEV);
    float*    sM  = (float*)(sm8 + OFF_M);
    float*    sLR = (float*)(sm8 + OFF_LR);
    float*    sWR = (float*)(sm8 + OFF_WR);
    float*    sINV= (float*)(sm8 + OFF_INV);

    const int tid = threadIdx.x, lane = tid & 31, warp = tid >> 5;
    const int g = lane >> 2, tg = lane & 3;
    const int wm = warp & 3, wn = warp >> 2;
    const int rm = wm * 32, cn = wn * 64, dn = wn * 32;

    // longest CTAs first (qblk descending)
    const int bx = blockIdx.x;
    const int qblk = 7 - (bx >> 6);
    const int bh = bx & 63;
    const int q0 = qblk * 128;
    const int ntiles = qblk + 1;

    const float* Qb = Q + (size_t)bh * SEQ * DH;
    const float* Kb = K + (size_t)bh * SEQ * DH;
    const float* Vb = V + (size_t)bh * SEQ * DH;
    const float maxk = g_maxk[bh];

    // ---- stage Q (raw fp32) into sPS; pe tables; zero taps ----
    for (int i = tid; i < 128 * 16; i += NTHR) {
        int r = i >> 4, c = (i & 15) * 4;
        *(float4*)(sPS + r * PS_STRIDE + c) =
            *(const float4*)(Qb + (size_t)(q0 + r) * DH + c);
    }
    for (int i = tid; i < 33 * 16; i += NTHR) {
        int r = i >> 4, c = (i & 15) * 4;
        float4 a = *(const float4*)(PEK + r * DH + c);
        sPEK[r*66+c] = a.x; sPEK[r*66+c+1] = a.y; sPEK[r*66+c+2] = a.z; sPEK[r*66+c+3] = a.w;
        float4 b = *(const float4*)(PEV + r * DH + c);
        sPEV[r*66+c] = b.x; sPEV[r*66+c+1] = b.y; sPEV[r*66+c+2] = b.z; sPEV[r*66+c+3] = b.w;
    }
    for (int i = tid; i < 128 * 34; i += NTHR) sW[i] = 0.f;
    __syncthreads();

    // ---- qpe[row][j] = q_row . pe_k[j]  (fp32) ----
    {
        int row = tid >> 1, half = tid & 1;
        float qreg[64];
        #pragma unroll
        for (int d = 0; d < 64; d++) qreg[d] = sPS[row * PS_STRIDE + d];
        int j0 = half * 16, jn = half ? 17 : 16;
        #pragma unroll 1
        for (int jj = 0; jj < jn; jj++) {
            int j = j0 + jj;
            float a = 0.f;
            #pragma unroll
            for (int d = 0; d < 64; d++) a = fmaf(qreg[d], sPEK[j*66+d], a);
            sQPE[row * 34 + j] = a;
        }
    }
    __syncthreads();

    // ---- M bound per row: ||q||*maxk + max_j qpe ----
    if (tid < 128) {
        const float* qr = sPS + tid * PS_STRIDE;
        float qn = 0.f;
        #pragma unroll
        for (int d = 0; d < 64; d++) qn = fmaf(qr[d], qr[d], qn);
        float mb = sQPE[tid * 34];
        #pragma unroll
        for (int j = 1; j < 33; j++) mb = fmaxf(mb, sQPE[tid * 34 + j]);
        sM[tid] = sqrtf(qn) * maxk + mb;
    }

    // ---- Q A-fragments, resident (tf32 rna) ----
    uint32_t qa[2][8][4];
    #pragma unroll
    for (int mt = 0; mt < 2; mt++)
        #pragma unroll
        for (int ks = 0; ks < 8; ks++) {
            int r = rm + 16*mt + g, c = 8*ks + tg;
            qa[mt][ks][0] = f2tf(sPS[r*PS_STRIDE + c]);
            qa[mt][ks][1] = f2tf(sPS[(r+8)*PS_STRIDE + c]);
            qa[mt][ks][2] = f2tf(sPS[r*PS_STRIDE + c + 4]);
            qa[mt][ks][3] = f2tf(sPS[(r+8)*PS_STRIDE + c + 4]);
        }
    __syncthreads();

    float Mrow[4];
    #pragma unroll
    for (int s = 0; s < 4; s++) {
        int row = rm + 16*(s>>1) + 8*(s&1) + g;
        Mrow[s] = sM[row];
    }

    // ================= single pass: QK -> e -> emit + PV =================
    float lloc[4] = {0.f, 0.f, 0.f, 0.f};
    float w0[4]   = {0.f, 0.f, 0.f, 0.f};
    float o[2][4][4] = {};

    for (int kt = 0; kt < ntiles; kt++) {
        const float* Kt = Kb + (size_t)kt * 128 * DH;
        const float* Vt = Vb + (size_t)kt * 128 * DH;
        __syncthreads();
        for (int i = tid; i < 128 * 16; i += NTHR) {
            int r = i >> 4, c = (i & 15) * 4;
            float4 v = *(const float4*)(Kt + (size_t)r * DH + c);
            uint4 u; u.x = f2tf(v.x); u.y = f2tf(v.y); u.z = f2tf(v.z); u.w = f2tf(v.w);
            *(uint4*)(ksu + r * KS_STRIDE + c) = u;
            float4 w = *(const float4*)(Vt + (size_t)r * DH + c);
            uint4 uw; uw.x = f2tf(w.x); uw.y = f2tf(w.y); uw.z = f2tf(w.z); uw.w = f2tf(w.w);
            *(uint4*)(vsu + r * VS_STRIDE + c) = uw;
        }
        __syncthreads();

        float acc[2][8][4] = {};
        #pragma unroll
        for (int nt = 0; nt < 8; nt++)
            #pragma unroll
            for (int ks = 0; ks < 8; ks++) {
                int base = (cn + 8*nt + g) * KS_STRIDE + 8*ks + tg;
                uint32_t b0 = ksu[base], b1 = ksu[base + 4];
                mma8(acc[0][nt], qa[0][ks], b0, b1);
                mma8(acc[1][nt], qa[1][ks], b0, b1);
            }

        // bias + mask + e = exp((s - M)*ISD); emit e to gmem + smem; l/w0/taps
        #pragma unroll
        for (int mt = 0; mt < 2; mt++)
            #pragma unroll
            for (int nt = 0; nt < 8; nt++) {
                float p[4];
                #pragma unroll
                for (int c = 0; c < 4; c++) {
                    int s = mt*2 + (c>>1);
                    int row = rm + 16*mt + 8*(c>>1) + g;
                    int col = kt*128 + cn + 8*nt + 2*tg + (c&1);
                    int qg = q0 + row;
                    float v = NEGINF;
                    if (col <= qg) {
                        int j = col - qg + 32; j = j < 0 ? 0 : j;
                        v = acc[mt][nt][c] + sQPE[row*34 + j];
                    }
                    float e = __expf((v - Mrow[s]) * ISD);
                    p[c] = e;
                    lloc[s] += e;
                    if (col <= qg - 32) w0[s] += e;
                    else if (col <= qg) sW[row*34 + (col - qg + 32)] = e;
                }
                int rowL = rm + 16*mt + g, rowH = rowL + 8;
                int colb = kt*128 + cn + 8*nt + 2*tg;
                *(float2*)(Pout + ((size_t)bh*SEQ + q0 + rowL)*SEQ + colb) = make_float2(p[0], p[1]);
                *(float2*)(Pout + ((size_t)bh*SEQ + q0 + rowH)*SEQ + colb) = make_float2(p[2], p[3]);
                int kloc = cn + 8*nt + 2*tg;
                uint2 u01; u01.x = f2tf(p[0]); u01.y = f2tf(p[1]);
                uint2 u23; u23.x = f2tf(p[2]); u23.y = f2tf(p[3]);
                *(uint2*)(psu + rowL*PS_STRIDE + kloc) = u01;
                *(uint2*)(psu + rowH*PS_STRIDE + kloc) = u23;
            }
        __syncthreads();

        // PV: O[rm..rm+31][dn..dn+31] += E_tile x V_tile (unnormalized)
        #pragma unroll 2
        for (int ks = 0; ks < 16; ks++) {
            uint32_t pa[2][4];
            #pragma unroll
            for (int mt = 0; mt < 2; mt++) {
                int r = rm + 16*mt + g, c = 8*ks + tg;
                pa[mt][0] = psu[r*PS_STRIDE + c];
                pa[mt][1] = psu[(r+8)*PS_STRIDE + c];
                pa[mt][2] = psu[r*PS_STRIDE + c + 4];
                pa[mt][3] = psu[(r+8)*PS_STRIDE + c + 4];
            }
            #pragma unroll
            for (int nt = 0; nt < 4; nt++) {
                uint32_t b0 = vsu[(8*ks + tg) * VS_STRIDE + dn + 8*nt + g];
                uint32_t b1 = vsu[(8*ks + tg + 4) * VS_STRIDE + dn + 8*nt + g];
                mma8(o[0][nt], pa[0], b0, b1);
                mma8(o[1][nt], pa[1], b0, b1);
            }
        }
    }
    __syncthreads();

    // ---- l reduce (quad + cross-warp) -> invl ----
    #pragma unroll
    for (int s = 0; s < 4; s++) {
        lloc[s] += __shfl_xor_sync(0xffffffffu, lloc[s], 1);
        lloc[s] += __shfl_xor_sync(0xffffffffu, lloc[s], 2);
        w0[s]   += __shfl_xor_sync(0xffffffffu, w0[s], 1);
        w0[s]   += __shfl_xor_sync(0xffffffffu, w0[s], 2);
    }
    if (tg == 0)
        #pragma unroll
        for (int s = 0; s < 4; s++) {
            int row = rm + 16*(s>>1) + 8*(s&1) + g;
            sLR[row*2 + wn] = lloc[s];
            sWR[row*2 + wn] = w0[s];
        }
    __syncthreads();
    float invl[4], w0f[4];
    #pragma unroll
    for (int s = 0; s < 4; s++) {
        int row = rm + 16*(s>>1) + 8*(s&1) + g;
        invl[s] = 1.f / (sLR[row*2] + sLR[row*2+1]);
        w0f[s]  = (sWR[row*2] + sWR[row*2+1]) * invl[s];
    }
    if (tg == 0 && wn == 0)
        #pragma unroll
        for (int s = 0; s < 4; s++) {
            int row = rm + 16*(s>>1) + 8*(s&1) + g;
            sINV[row] = invl[s];
        }

    // ---- normalize O ----
    #pragma unroll
    for (int mt = 0; mt < 2; mt++)
        #pragma unroll
        for (int nt = 0; nt < 4; nt++)
            #pragma unroll
            for (int c = 0; c < 4; c++)
                o[mt][nt][c] *= invl[mt*2 + (c>>1)];

    // ---- rel-pos value epilogue: o += sum_j (e_j*invl) * pe_v[j] ----
    #pragma unroll 1
    for (int j = 0; j <= 32; j++) {
        float wj[4];
        #pragma unroll
        for (int s = 0; s < 4; s++) {
            int row = rm + 16*(s>>1) + 8*(s&1) + g;
            wj[s] = (j == 0) ? w0f[s] : sW[row*34 + j] * invl[s];
        }
        #pragma unroll
        for (int nt = 0; nt < 4; nt++) {
            float pe0 = sPEV[j*66 + dn + 8*nt + 2*tg];
            float pe1 = sPEV[j*66 + dn + 8*nt + 2*tg + 1];
            #pragma unroll
            for (int mt = 0; mt < 2; mt++) {
                o[mt][nt][0] = fmaf(wj[mt*2+0], pe0, o[mt][nt][0]);
                o[mt][nt][1] = fmaf(wj[mt*2+0], pe1, o[mt][nt][1]);
                o[mt][nt][2] = fmaf(wj[mt*2+1], pe0, o[mt][nt][2]);
                o[mt][nt][3] = fmaf(wj[mt*2+1], pe1, o[mt][nt][3]);
            }
        }
    }

    // ---- write output ----
    #pragma unroll
    for (int mt = 0; mt < 2; mt++)
        #pragma unroll
        for (int nt = 0; nt < 4; nt++) {
            int rowL = rm + 16*mt + g, rowH = rowL + 8;
            int colb = dn + 8*nt + 2*tg;
            *(float2*)(Out + ((size_t)bh*SEQ + q0 + rowL)*DH + colb) = make_float2(o[mt][nt][0], o[mt][nt][1]);
            *(float2*)(Out + ((size_t)bh*SEQ + q0 + rowH)*DH + colb) = make_float2(o[mt][nt][2], o[mt][nt][3]);
        }

    __syncthreads();   // sINV visible + all e-writes to gmem visible block-wide

    // ---- in-place rescale of Pout (e -> p = e/l), L2-hot ----
    {
        const int cols = ntiles * 128;
        for (int r = warp; r < 128; r += 8) {
            float inv = sINV[r];
            float4* rowp = (float4*)(Pout + ((size_t)bh*SEQ + q0 + r)*SEQ);
            for (int c4 = lane; c4 < (cols >> 2); c4 += 32) {
                float4 v = rowp[c4];
                v.x *= inv; v.y *= inv; v.z *= inv; v.w *= inv;
                rowp[c4] = v;
            }
        }
    }

    // ---- zero-fill masked p region ----
    int zc = SEQ - ntiles * 128;
    if (zc > 0) {
        int zq = zc >> 2;
        float4 z = make_float4(0.f, 0.f, 0.f, 0.f);
        float* base = Pout + ((size_t)bh*SEQ + q0)*SEQ + ntiles*128;
        for (int i = tid; i < 128 * zq; i += NTHR) {
            int r = i / zq, c = (i - r * zq) * 4;
            *(float4*)(base + (size_t)r * SEQ + c) = z;
        }
    }
}

extern "C" void kernel_launch(void* const* d_in, const int* in_sizes, int n_in,
                              void* d_out, int out_size)
{
    (void)in_sizes; (void)n_in; (void)out_size;
    const float* Q   = (const float*)d_in[0];
    const float* K   = (const float*)d_in[1];
    const float* V   = (const float*)d_in[2];
    const float* PEK = (const float*)d_in[3];
    const float* PEV = (const float*)d_in[4];
    float* Out  = (float*)d_out;
    float* Pout = Out + (size_t)BH * SEQ * DH;

    knorm_kernel<<<BH, 256>>>(K);
    cudaFuncSetAttribute(relattn_mma, cudaFuncAttributeMaxDynamicSharedMemorySize, SMEM_TOTAL);
    relattn_mma<<<512, NTHR, SMEM_TOTAL>>>(Q, K, V, PEK, PEV, Out, Pout);
}

// round 5
// speedup vs baseline: 1.1087x; 1.1087x over previous
#include <cuda_runtime.h>
#include <math.h>
#include <stdint.h>

// B=4,H=16 -> BH=64; S=1024; D=64; rel-pos P=32
#define BH   64
#define SEQ  1024
#define DH   64
#define NTHR 512
#define ISD  0.125f
#define NEGINF (-INFINITY)

// smem layout (bytes)
#define KS_STRIDE 68
#define VS_STRIDE 72
#define QT_STRIDE 68
#define PS_STRIDE 132
#define OFF_KS   0                          // K tile tf32 [128][68]      34816
#define OFF_VS   34816                      // V tile tf32 [128][72]      36864
#define OFF_QT   71680                      // Q tile tf32 [128][68]      34816
#define OFF_PS   106496                     // e tile tf32 [128][132] (+ Q fp32 staging)
#define OFF_QPE  174080                     // qpe [128][34] f32          17408
#define OFF_W    191488                     // tap e-values [128][34]     17408
#define OFF_PEK  208896                     // pe_k [33][66] f32           8712
#define OFF_PEV  217608                     //                             8712
#define OFF_M    226320                     // M bound per row [128]        512
#define SMEM_TOTAL 226832

__device__ float g_maxk[BH];

static __device__ __forceinline__ uint32_t f2tf(float x) {
    uint32_t r; asm("cvt.rna.tf32.f32 %0, %1;" : "=r"(r) : "f"(x)); return r;
}
static __device__ __forceinline__ void mma8(float* d, const uint32_t* a,
                                            uint32_t b0, uint32_t b1) {
    asm volatile("mma.sync.aligned.m16n8k8.row.col.f32.tf32.tf32.f32 "
        "{%0,%1,%2,%3},{%4,%5,%6,%7},{%8,%9},{%0,%1,%2,%3};"
        : "+f"(d[0]), "+f"(d[1]), "+f"(d[2]), "+f"(d[3])
        : "r"(a[0]), "r"(a[1]), "r"(a[2]), "r"(a[3]), "r"(b0), "r"(b1));
}

// ---- precompute: per-bh max ||k_row|| ----
__global__ __launch_bounds__(256, 4)
void knorm_kernel(const float* __restrict__ K)
{
    __shared__ float red[8];
    const int bh = blockIdx.x, tid = threadIdx.x;
    const float* Kb = K + (size_t)bh * SEQ * DH;
    float mx = 0.f;
    for (int r = tid; r < SEQ; r += 256) {
        const float4* kr = (const float4*)(Kb + (size_t)r * DH);
        float s = 0.f;
        #pragma unroll
        for (int i = 0; i < 16; i++) {
            float4 v = kr[i];
            s += v.x*v.x + v.y*v.y + v.z*v.z + v.w*v.w;
        }
        mx = fmaxf(mx, s);
    }
    #pragma unroll
    for (int o = 16; o > 0; o >>= 1) mx = fmaxf(mx, __shfl_xor_sync(0xffffffffu, mx, o));
    if ((tid & 31) == 0) red[tid >> 5] = mx;
    __syncthreads();
    if (tid == 0) {
        float m = red[0];
        #pragma unroll
        for (int i = 1; i < 8; i++) m = fmaxf(m, red[i]);
        g_maxk[bh] = sqrtf(m);
    }
}

__global__ __launch_bounds__(NTHR, 1)
void relattn_mma(const float* __restrict__ Q, const float* __restrict__ K,
                 const float* __restrict__ V, const float* __restrict__ PEK,
                 const float* __restrict__ PEV,
                 float* __restrict__ Out, float* __restrict__ Pout)
{
    extern __shared__ char sm8[];
    uint32_t* ksu = (uint32_t*)(sm8 + OFF_KS);
    uint32_t* vsu = (uint32_t*)(sm8 + OFF_VS);
    uint32_t* qsu = (uint32_t*)(sm8 + OFF_QT);
    float*    sPS = (float*)(sm8 + OFF_PS);
    uint32_t* psu = (uint32_t*)(sm8 + OFF_PS);
    float*    sQPE= (float*)(sm8 + OFF_QPE);
    float*    sW  = (float*)(sm8 + OFF_W);
    float*    sPEK= (float*)(sm8 + OFF_PEK);
    float*    sPEV= (float*)(sm8 + OFF_PEV);
    float*    sM  = (float*)(sm8 + OFF_M);
    // reduction scratch overlays the e-tile (dead after last PV)
    float*    sLR = (float*)(sm8 + OFF_PS);            // [128][4]
    float*    sWR = (float*)(sm8 + OFF_PS) + 512;      // [128][4]
    float*    sINV= (float*)(sm8 + OFF_PS) + 1024;     // [128]

    const int tid = threadIdx.x, lane = tid & 31, warp = tid >> 5;
    const int g = lane >> 2, tg = lane & 3;
    const int wm = warp & 3, wn = warp >> 2;           // 4 x 4 warp grid
    const int rm = wm * 32, cn = wn * 32, dn = wn * 16;

    // longest CTAs first (qblk descending)
    const int bx = blockIdx.x;
    const int qblk = 7 - (bx >> 6);
    const int bh = bx & 63;
    const int q0 = qblk * 128;
    const int ntiles = qblk + 1;

    const float* Qb = Q + (size_t)bh * SEQ * DH;
    const float* Kb = K + (size_t)bh * SEQ * DH;
    const float* Vb = V + (size_t)bh * SEQ * DH;
    const float maxk = g_maxk[bh];

    // ---- stage Q (raw fp32) into sPS; pe tables; zero taps ----
    for (int i = tid; i < 128 * 16; i += NTHR) {
        int r = i >> 4, c = (i & 15) * 4;
        *(float4*)(sPS + r * PS_STRIDE + c) =
            *(const float4*)(Qb + (size_t)(q0 + r) * DH + c);
    }
    for (int i = tid; i < 33 * 16; i += NTHR) {
        int r = i >> 4, c = (i & 15) * 4;
        float4 a = *(const float4*)(PEK + r * DH + c);
        sPEK[r*66+c] = a.x; sPEK[r*66+c+1] = a.y; sPEK[r*66+c+2] = a.z; sPEK[r*66+c+3] = a.w;
        float4 b = *(const float4*)(PEV + r * DH + c);
        sPEV[r*66+c] = b.x; sPEV[r*66+c+1] = b.y; sPEV[r*66+c+2] = b.z; sPEV[r*66+c+3] = b.w;
    }
    for (int i = tid; i < 128 * 34; i += NTHR) sW[i] = 0.f;
    __syncthreads();

    // ---- qpe[row][j] = q_row . pe_k[j]  (fp32); 4 threads per row ----
    {
        int row = tid >> 2, quarter = tid & 3;
        const float* qr = sPS + row * PS_STRIDE;
        int j0 = quarter * 8, jn = (quarter == 3) ? 9 : 8;
        #pragma unroll 1
        for (int jj = 0; jj < jn; jj++) {
            int j = j0 + jj;
            const float* pk = sPEK + j * 66;
            float a = 0.f;
            #pragma unroll
            for (int d = 0; d < 64; d++) a = fmaf(qr[d], pk[d], a);
            sQPE[row * 34 + j] = a;
        }
    }
    __syncthreads();

    // ---- M bound per row + convert Q -> tf32 tile ----
    if (tid < 128) {
        const float* qr = sPS + tid * PS_STRIDE;
        float qn = 0.f;
        #pragma unroll
        for (int d = 0; d < 64; d++) qn = fmaf(qr[d], qr[d], qn);
        float mb = sQPE[tid * 34];
        #pragma unroll
        for (int j = 1; j < 33; j++) mb = fmaxf(mb, sQPE[tid * 34 + j]);
        sM[tid] = sqrtf(qn) * maxk + mb;
    }
    for (int i = tid; i < 128 * 16; i += NTHR) {
        int r = i >> 4, c = (i & 15) * 4;
        const float* s = sPS + r * PS_STRIDE + c;
        uint4 u; u.x = f2tf(s[0]); u.y = f2tf(s[1]); u.z = f2tf(s[2]); u.w = f2tf(s[3]);
        *(uint4*)(qsu + r * QT_STRIDE + c) = u;
    }
    __syncthreads();

    float Mrow[4];
    #pragma unroll
    for (int s = 0; s < 4; s++) {
        int row = rm + 16*(s>>1) + 8*(s&1) + g;
        Mrow[s] = sM[row];
    }

    // ================= single pass: QK -> e -> emit + PV =================
    float lloc[4] = {0.f, 0.f, 0.f, 0.f};
    float w0[4]   = {0.f, 0.f, 0.f, 0.f};
    float o[2][2][4] = {};

    for (int kt = 0; kt < ntiles; kt++) {
        const float* Kt = Kb + (size_t)kt * 128 * DH;
        const float* Vt = Vb + (size_t)kt * 128 * DH;

        // prefetch K/V into regs (overlaps previous tile's PV)
        float4 kreg[4], vreg[4];
        #pragma unroll
        for (int n = 0; n < 4; n++) {
            int i = tid + n * NTHR;
            int r = i >> 4, c = (i & 15) * 4;
            kreg[n] = *(const float4*)(Kt + (size_t)r * DH + c);
            vreg[n] = *(const float4*)(Vt + (size_t)r * DH + c);
        }
        __syncthreads();
        #pragma unroll
        for (int n = 0; n < 4; n++) {
            int i = tid + n * NTHR;
            int r = i >> 4, c = (i & 15) * 4;
            uint4 u; u.x = f2tf(kreg[n].x); u.y = f2tf(kreg[n].y);
            u.z = f2tf(kreg[n].z); u.w = f2tf(kreg[n].w);
            *(uint4*)(ksu + r * KS_STRIDE + c) = u;
            uint4 w; w.x = f2tf(vreg[n].x); w.y = f2tf(vreg[n].y);
            w.z = f2tf(vreg[n].z); w.w = f2tf(vreg[n].w);
            *(uint4*)(vsu + r * VS_STRIDE + c) = w;
        }
        __syncthreads();

        // ---- score MMAs: 32 rows x 32 cols per warp ----
        float acc[2][4][4] = {};
        #pragma unroll
        for (int ks = 0; ks < 8; ks++) {
            uint32_t qa[2][4];
            #pragma unroll
            for (int mt = 0; mt < 2; mt++) {
                int r = rm + 16*mt + g, c = 8*ks + tg;
                qa[mt][0] = qsu[r*QT_STRIDE + c];
                qa[mt][1] = qsu[(r+8)*QT_STRIDE + c];
                qa[mt][2] = qsu[r*QT_STRIDE + c + 4];
                qa[mt][3] = qsu[(r+8)*QT_STRIDE + c + 4];
            }
            #pragma unroll
            for (int nt = 0; nt < 4; nt++) {
                int base = (cn + 8*nt + g) * KS_STRIDE + 8*ks + tg;
                uint32_t b0 = ksu[base], b1 = ksu[base + 4];
                mma8(acc[0][nt], qa[0], b0, b1);
                mma8(acc[1][nt], qa[1], b0, b1);
            }
        }

        // ---- bias + mask + e; emit e to gmem + smem; l/w0/taps ----
        #pragma unroll
        for (int mt = 0; mt < 2; mt++)
            #pragma unroll
            for (int nt = 0; nt < 4; nt++) {
                float p[4];
                #pragma unroll
                for (int c = 0; c < 4; c++) {
                    int s = mt*2 + (c>>1);
                    int row = rm + 16*mt + 8*(c>>1) + g;
                    int col = kt*128 + cn + 8*nt + 2*tg + (c&1);
                    int qg = q0 + row;
                    float v = NEGINF;
                    if (col <= qg) {
                        int j = col - qg + 32; j = j < 0 ? 0 : j;
                        v = acc[mt][nt][c] + sQPE[row*34 + j];
                    }
                    float e = __expf((v - Mrow[s]) * ISD);
                    p[c] = e;
                    lloc[s] += e;
                    if (col <= qg - 32) w0[s] += e;
                    else if (col <= qg) sW[row*34 + (col - qg + 32)] = e;
                }
                int rowL = rm + 16*mt + g, rowH = rowL + 8;
                int colb = kt*128 + cn + 8*nt + 2*tg;
                *(float2*)(Pout + ((size_t)bh*SEQ + q0 + rowL)*SEQ + colb) = make_float2(p[0], p[1]);
                *(float2*)(Pout + ((size_t)bh*SEQ + q0 + rowH)*SEQ + colb) = make_float2(p[2], p[3]);
                int kloc = cn + 8*nt + 2*tg;
                uint2 u01; u01.x = f2tf(p[0]); u01.y = f2tf(p[1]);
                uint2 u23; u23.x = f2tf(p[2]); u23.y = f2tf(p[3]);
                *(uint2*)(psu + rowL*PS_STRIDE + kloc) = u01;
                *(uint2*)(psu + rowH*PS_STRIDE + kloc) = u23;
            }
        __syncthreads();

        // ---- PV: O[rm..rm+31][dn..dn+15] += E_tile x V_tile ----
        #pragma unroll 2
        for (int ks = 0; ks < 16; ks++) {
            uint32_t pa[2][4];
            #pragma unroll
            for (int mt = 0; mt < 2; mt++) {
                int r = rm + 16*mt + g, c = 8*ks + tg;
                pa[mt][0] = psu[r*PS_STRIDE + c];
                pa[mt][1] = psu[(r+8)*PS_STRIDE + c];
                pa[mt][2] = psu[r*PS_STRIDE + c + 4];
                pa[mt][3] = psu[(r+8)*PS_STRIDE + c + 4];
            }
            #pragma unroll
            for (int nt = 0; nt < 2; nt++) {
                uint32_t b0 = vsu[(8*ks + tg) * VS_STRIDE + dn + 8*nt + g];
                uint32_t b1 = vsu[(8*ks + tg + 4) * VS_STRIDE + dn + 8*nt + g];
                mma8(o[0][nt], pa[0], b0, b1);
                mma8(o[1][nt], pa[1], b0, b1);
            }
        }
    }
    __syncthreads();   // e-tile dead; scratch overlay safe

    // ---- l / w0 reduce (quad + cross-wn) ----
    #pragma unroll
    for (int s = 0; s < 4; s++) {
        lloc[s] += __shfl_xor_sync(0xffffffffu, lloc[s], 1);
        lloc[s] += __shfl_xor_sync(0xffffffffu, lloc[s], 2);
        w0[s]   += __shfl_xor_sync(0xffffffffu, w0[s], 1);
        w0[s]   += __shfl_xor_sync(0xffffffffu, w0[s], 2);
    }
    if (tg == 0)
        #pragma unroll
        for (int s = 0; s < 4; s++) {
            int row = rm + 16*(s>>1) + 8*(s&1) + g;
            sLR[row*4 + wn] = lloc[s];
            sWR[row*4 + wn] = w0[s];
        }
    __syncthreads();
    float invl[4], w0f[4];
    #pragma unroll
    for (int s = 0; s < 4; s++) {
        int row = rm + 16*(s>>1) + 8*(s&1) + g;
        invl[s] = 1.f / (sLR[row*4] + sLR[row*4+1] + sLR[row*4+2] + sLR[row*4+3]);
        w0f[s]  = (sWR[row*4] + sWR[row*4+1] + sWR[row*4+2] + sWR[row*4+3]) * invl[s];
    }
    if (tg == 0 && wn == 0)
        #pragma unroll
        for (int s = 0; s < 4; s++) {
            int row = rm + 16*(s>>1) + 8*(s&1) + g;
            sINV[row] = invl[s];
        }

    // ---- normalize O ----
    #pragma unroll
    for (int mt = 0; mt < 2; mt++)
        #pragma unroll
        for (int nt = 0; nt < 2; nt++)
            #pragma unroll
            for (int c = 0; c < 4; c++)
                o[mt][nt][c] *= invl[mt*2 + (c>>1)];

    // ---- rel-pos value epilogue: o += sum_j (e_j*invl) * pe_v[j] ----
    #pragma unroll 1
    for (int j = 0; j <= 32; j++) {
        float wj[4];
        #pragma unroll
        for (int s = 0; s < 4; s++) {
            int row = rm + 16*(s>>1) + 8*(s&1) + g;
            wj[s] = (j == 0) ? w0f[s] : sW[row*34 + j] * invl[s];
        }
        #pragma unroll
        for (int nt = 0; nt < 2; nt++) {
            float pe0 = sPEV[j*66 + dn + 8*nt + 2*tg];
            float pe1 = sPEV[j*66 + dn + 8*nt + 2*tg + 1];
            #pragma unroll
            for (int mt = 0; mt < 2; mt++) {
                o[mt][nt][0] = fmaf(wj[mt*2+0], pe0, o[mt][nt][0]);
                o[mt][nt][1] = fmaf(wj[mt*2+0], pe1, o[mt][nt][1]);
                o[mt][nt][2] = fmaf(wj[mt*2+1], pe0, o[mt][nt][2]);
                o[mt][nt][3] = fmaf(wj[mt*2+1], pe1, o[mt][nt][3]);
            }
        }
    }

    // ---- write output ----
    #pragma unroll
    for (int mt = 0; mt < 2; mt++)
        #pragma unroll
        for (int nt = 0; nt < 2; nt++) {
            int rowL = rm + 16*mt + g, rowH = rowL + 8;
            int colb = dn + 8*nt + 2*tg;
            *(float2*)(Out + ((size_t)bh*SEQ + q0 + rowL)*DH + colb) = make_float2(o[mt][nt][0], o[mt][nt][1]);
            *(float2*)(Out + ((size_t)bh*SEQ + q0 + rowH)*DH + colb) = make_float2(o[mt][nt][2], o[mt][nt][3]);
        }

    __syncthreads();   // sINV visible + e-writes to gmem visible block-wide

    // ---- in-place rescale of Pout (e -> p = e/l), L2-hot ----
    {
        const int cols = ntiles * 128;
        for (int r = warp; r < 128; r += 16) {
            float inv = sINV[r];
            float4* rowp = (float4*)(Pout + ((size_t)bh*SEQ + q0 + r)*SEQ);
            for (int c4 = lane; c4 < (cols >> 2); c4 += 32) {
                float4 v = rowp[c4];
                v.x *= inv; v.y *= inv; v.z *= inv; v.w *= inv;
                rowp[c4] = v;
            }
        }
    }

    // ---- zero-fill masked p region ----
    int zc = SEQ - ntiles * 128;
    if (zc > 0) {
        int zq = zc >> 2;
        float4 z = make_float4(0.f, 0.f, 0.f, 0.f);
        float* base = Pout + ((size_t)bh*SEQ + q0)*SEQ + ntiles*128;
        for (int i = tid; i < 128 * zq; i += NTHR) {
            int r = i / zq, c = (i - r * zq) * 4;
            *(float4*)(base + (size_t)r * SEQ + c) = z;
        }
    }
}

extern "C" void kernel_launch(void* const* d_in, const int* in_sizes, int n_in,
                              void* d_out, int out_size)
{
    (void)in_sizes; (void)n_in; (void)out_size;
    const float* Q   = (const float*)d_in[0];
    const float* K   = (const float*)d_in[1];
    const float* V   = (const float*)d_in[2];
    const float* PEK = (const float*)d_in[3];
    const float* PEV = (const float*)d_in[4];
    float* Out  = (float*)d_out;
    float* Pout = Out + (size_t)BH * SEQ * DH;

    knorm_kernel<<<BH, 256>>>(K);
    cudaFuncSetAttribute(relattn_mma, cudaFuncAttributeMaxDynamicSharedMemorySize, SMEM_TOTAL);
    relattn_mma<<<512, NTHR, SMEM_TOTAL>>>(Q, K, V, PEK, PEV, Out, Pout);
}

// round 7
// speedup vs baseline: 1.1578x; 1.0443x over previous
#include <cuda_runtime.h>
#include <cuda_fp16.h>
#include <math.h>
#include <stdint.h>

// B=4,H=16 -> BH=64; S=1024; D=64; rel-pos P=32
#define BH   64
#define SEQ  1024
#define DH   64
#define NTHR 512
#define ISD  0.125f
#define NEGINF (-INFINITY)

// half-tile strides (in halves)
#define KH_STRH 72     // 36 words
#define QH_STRH 72
#define VT_STRH 136    // 68 words
#define EH_STRH 136
#define QSTG_STR 68    // fp32 staging stride (272B, 16B-divisible for float4)

// smem layout (bytes)
#define OFF_KH   0                       // K fp16 [128][72]     18432
#define OFF_QH   18432                   // Q fp16 [128][72]     18432
#define OFF_VT   36864                   // V^T fp16 [64][136]   17408
#define OFF_EH   54272                   // e fp16 [128][136]    34816  (also Q fp32 staging [128][68])
#define OFF_QPE  89088                   // qpe [128][34] f32    17408
#define OFF_W    106496                  // taps [128][34] f32   17408
#define OFF_PEK  123904                  // pe_k [33][66] f32     8720
#define OFF_PEV  132624                  //                       8720
#define OFF_M    141344                  // M bound [128]          512
#define SMEM_TOTAL 141856

__device__ float g_maxk[BH];

static __device__ __forceinline__ uint32_t h2u(float a, float b) {
    __half2 h = __floats2half2_rn(a, b);
    return *reinterpret_cast<uint32_t*>(&h);
}
static __device__ __forceinline__ void mma16(float* d, const uint32_t* a,
                                             uint32_t b0, uint32_t b1) {
    asm volatile("mma.sync.aligned.m16n8k16.row.col.f32.f16.f16.f32 "
        "{%0,%1,%2,%3},{%4,%5,%6,%7},{%8,%9},{%0,%1,%2,%3};"
        : "+f"(d[0]), "+f"(d[1]), "+f"(d[2]), "+f"(d[3])
        : "r"(a[0]), "r"(a[1]), "r"(a[2]), "r"(a[3]), "r"(b0), "r"(b1));
}

// ---- precompute: per-bh max ||k_row|| ----
__global__ __launch_bounds__(256, 4)
void knorm_kernel(const float* __restrict__ K)
{
    __shared__ float red[8];
    const int bh = blockIdx.x, tid = threadIdx.x;
    const float* Kb = K + (size_t)bh * SEQ * DH;
    float mx = 0.f;
    for (int r = tid; r < SEQ; r += 256) {
        const float4* kr = (const float4*)(Kb + (size_t)r * DH);
        float s = 0.f;
        #pragma unroll
        for (int i = 0; i < 16; i++) {
            float4 v = kr[i];
            s += v.x*v.x + v.y*v.y + v.z*v.z + v.w*v.w;
        }
        mx = fmaxf(mx, s);
    }
    #pragma unroll
    for (int o = 16; o > 0; o >>= 1) mx = fmaxf(mx, __shfl_xor_sync(0xffffffffu, mx, o));
    if ((tid & 31) == 0) red[tid >> 5] = mx;
    __syncthreads();
    if (tid == 0) {
        float m = red[0];
        #pragma unroll
        for (int i = 1; i < 8; i++) m = fmaxf(m, red[i]);
        g_maxk[bh] = sqrtf(m);
    }
}

__global__ __launch_bounds__(NTHR, 1)
void relattn_mma(const float* __restrict__ Q, const float* __restrict__ K,
                 const float* __restrict__ V, const float* __restrict__ PEK,
                 const float* __restrict__ PEV,
                 float* __restrict__ Out, float* __restrict__ Pout)
{
    extern __shared__ char sm8[];
    uint32_t* kw  = (uint32_t*)(sm8 + OFF_KH);   // word view (36/row)
    uint32_t* qw  = (uint32_t*)(sm8 + OFF_QH);
    uint32_t* vw  = (uint32_t*)(sm8 + OFF_VT);   // 68/row (d-major)
    uint32_t* ew  = (uint32_t*)(sm8 + OFF_EH);   // 68/row
    float*    qstg= (float*)(sm8 + OFF_EH);      // fp32 Q staging [128][68] (dead before EH use)
    float*    sQPE= (float*)(sm8 + OFF_QPE);
    float*    sW  = (float*)(sm8 + OFF_W);
    float*    sPEK= (float*)(sm8 + OFF_PEK);
    float*    sPEV= (float*)(sm8 + OFF_PEV);
    float*    sM  = (float*)(sm8 + OFF_M);
    // reduction scratch overlays e-tile (dead after last PV)
    float*    sLR = (float*)(sm8 + OFF_EH);            // [128][4]
    float*    sWR = (float*)(sm8 + OFF_EH) + 512;      // [128][4]
    float*    sINV= (float*)(sm8 + OFF_EH) + 1024;     // [128]

    const int tid = threadIdx.x, lane = tid & 31, warp = tid >> 5;
    const int g = lane >> 2, tg = lane & 3;
    const int wm = warp & 3, wn = warp >> 2;           // 4 x 4 warp grid
    const int rm = wm * 32, cn = wn * 32, dn = wn * 16;

    // longest CTAs first (qblk descending)
    const int bx = blockIdx.x;
    const int qblk = 7 - (bx >> 6);
    const int bh = bx & 63;
    const int q0 = qblk * 128;
    const int ntiles = qblk + 1;

    const float* Qb = Q + (size_t)bh * SEQ * DH;
    const float* Kb = K + (size_t)bh * SEQ * DH;
    const float* Vb = V + (size_t)bh * SEQ * DH;
    const float maxk = g_maxk[bh];

    // ---- stage Q (fp32) + pe tables; zero taps ----
    for (int i = tid; i < 128 * 16; i += NTHR) {
        int r = i >> 4, c = (i & 15) * 4;
        *(float4*)(qstg + r * QSTG_STR + c) =
            *(const float4*)(Qb + (size_t)(q0 + r) * DH + c);
    }
    for (int i = tid; i < 33 * 16; i += NTHR) {
        int r = i >> 4, c = (i & 15) * 4;
        float4 a = *(const float4*)(PEK + r * DH + c);
        sPEK[r*66+c] = a.x; sPEK[r*66+c+1] = a.y; sPEK[r*66+c+2] = a.z; sPEK[r*66+c+3] = a.w;
        float4 b = *(const float4*)(PEV + r * DH + c);
        sPEV[r*66+c] = b.x; sPEV[r*66+c+1] = b.y; sPEV[r*66+c+2] = b.z; sPEV[r*66+c+3] = b.w;
    }
    for (int i = tid; i < 128 * 34; i += NTHR) sW[i] = 0.f;
    __syncthreads();

    // ---- qpe[row][j] = q_row . pe_k[j]  (fp32); 4 threads per row ----
    {
        int row = tid >> 2, quarter = tid & 3;
        const float* qr = qstg + row * QSTG_STR;
        int j0 = quarter * 8, jn = (quarter == 3) ? 9 : 8;
        #pragma unroll 1
        for (int jj = 0; jj < jn; jj++) {
            int j = j0 + jj;
            const float* pk = sPEK + j * 66;
            float a = 0.f;
            #pragma unroll
            for (int d = 0; d < 64; d++) a = fmaf(qr[d], pk[d], a);
            sQPE[row * 34 + j] = a;
        }
    }
    __syncthreads();

    // ---- M bound per row + build Q fp16 tile ----
    if (tid < 128) {
        const float* qr = qstg + tid * QSTG_STR;
        float qn = 0.f;
        #pragma unroll
        for (int d = 0; d < 64; d++) qn = fmaf(qr[d], qr[d], qn);
        float mb = sQPE[tid * 34];
        #pragma unroll
        for (int j = 1; j < 33; j++) mb = fmaxf(mb, sQPE[tid * 34 + j]);
        sM[tid] = sqrtf(qn) * maxk + mb;
    }
    for (int i = tid; i < 128 * 16; i += NTHR) {
        int r = i >> 4, c = (i & 15) * 4;
        const float* s = qstg + r * QSTG_STR + c;
        uint2 u; u.x = h2u(s[0], s[1]); u.y = h2u(s[2], s[3]);
        *(uint2*)(qw + r * (QH_STRH/2) + c/2) = u;
    }
    __syncthreads();

    float Mrow[4];
    #pragma unroll
    for (int s = 0; s < 4; s++) {
        int row = rm + 16*(s>>1) + 8*(s&1) + g;
        Mrow[s] = sM[row];
    }

    // ================= single pass: QK -> e -> emit + PV =================
    float lloc[4] = {0.f, 0.f, 0.f, 0.f};
    float w0[4]   = {0.f, 0.f, 0.f, 0.f};
    float o[2][2][4] = {};
    const int vkp = tid & 63, vdb = (tid >> 6) * 8;   // V-transpose mapping

    for (int kt = 0; kt < ntiles; kt++) {
        const float* Kt = Kb + (size_t)kt * 128 * DH;
        const float* Vt = Vb + (size_t)kt * 128 * DH;

        // prefetch K/V into regs (overlaps previous tile's PV)
        float4 kreg[4], vreg[4];
        #pragma unroll
        for (int n = 0; n < 4; n++) {
            int i = tid + n * NTHR;
            int r = i >> 4, c = (i & 15) * 4;
            kreg[n] = *(const float4*)(Kt + (size_t)r * DH + c);
        }
        vreg[0] = *(const float4*)(Vt + (size_t)(2*vkp)   * DH + vdb);
        vreg[1] = *(const float4*)(Vt + (size_t)(2*vkp)   * DH + vdb + 4);
        vreg[2] = *(const float4*)(Vt + (size_t)(2*vkp+1) * DH + vdb);
        vreg[3] = *(const float4*)(Vt + (size_t)(2*vkp+1) * DH + vdb + 4);
        __syncthreads();
        #pragma unroll
        for (int n = 0; n < 4; n++) {
            int i = tid + n * NTHR;
            int r = i >> 4, c = (i & 15) * 4;
            uint2 u; u.x = h2u(kreg[n].x, kreg[n].y); u.y = h2u(kreg[n].z, kreg[n].w);
            *(uint2*)(kw + r * (KH_STRH/2) + c/2) = u;
        }
        {   // V transpose: half2(key0,key1) per d
            const float* v0 = (const float*)&vreg[0];
            const float* v1 = (const float*)&vreg[2];
            #pragma unroll
            for (int j = 0; j < 8; j++)
                vw[(vdb + j) * (VT_STRH/2) + vkp] = h2u(v0[j], v1[j]);
        }
        __syncthreads();

        const bool live = (kt*128 + cn) <= (q0 + rm + 31);

        // ---- score MMAs: 32 rows x 32 cols per warp ----
        float acc[2][4][4] = {};
        if (live) {
            #pragma unroll
            for (int ks = 0; ks < 4; ks++) {
                uint32_t qa[2][4];
                #pragma unroll
                for (int mt = 0; mt < 2; mt++) {
                    int base = (rm + 16*mt + g) * (QH_STRH/2) + 8*ks + tg;
                    qa[mt][0] = qw[base];
                    qa[mt][1] = qw[base + 8*(QH_STRH/2)];
                    qa[mt][2] = qw[base + 4];
                    qa[mt][3] = qw[base + 8*(QH_STRH/2) + 4];
                }
                #pragma unroll
                for (int nt = 0; nt < 4; nt++) {
                    int bb = (cn + 8*nt + g) * (KH_STRH/2) + 8*ks + tg;
                    uint32_t b0 = kw[bb], b1 = kw[bb + 4];
                    mma16(acc[0][nt], qa[0], b0, b1);
                    mma16(acc[1][nt], qa[1], b0, b1);
                }
            }
        }

        // ---- bias + mask + e; emit e to gmem + smem; l/w0/taps ----
        if (live) {
            #pragma unroll
            for (int mt = 0; mt < 2; mt++)
                #pragma unroll
                for (int nt = 0; nt < 4; nt++) {
                    float p[4];
                    #pragma unroll
                    for (int c = 0; c < 4; c++) {
                        int s = mt*2 + (c>>1);
                        int row = rm + 16*mt + 8*(c>>1) + g;
                        int col = kt*128 + cn + 8*nt + 2*tg + (c&1);
                        int qg = q0 + row;
                        float v = NEGINF;
                        if (col <= qg) {
                            int j = col - qg + 32; j = j < 0 ? 0 : j;
                            v = acc[mt][nt][c] + sQPE[row*34 + j];
                        }
                        float e = __expf((v - Mrow[s]) * ISD);
                        p[c] = e;
                        lloc[s] += e;
                        if (col <= qg - 32) w0[s] += e;
                        else if (col <= qg) sW[row*34 + (col - qg + 32)] = e;
                    }
                    int rowL = rm + 16*mt + g, rowH = rowL + 8;
                    int colb = kt*128 + cn + 8*nt + 2*tg;
                    *(float2*)(Pout + ((size_t)bh*SEQ + q0 + rowL)*SEQ + colb) = make_float2(p[0], p[1]);
                    *(float2*)(Pout + ((size_t)bh*SEQ + q0 + rowH)*SEQ + colb) = make_float2(p[2], p[3]);
                    int wc = (cn >> 1) + 4*nt + tg;
                    ew[rowL * (EH_STRH/2) + wc] = h2u(p[0], p[1]);
                    ew[rowH * (EH_STRH/2) + wc] = h2u(p[2], p[3]);
                }
        } else {
            #pragma unroll
            for (int mt = 0; mt < 2; mt++)
                #pragma unroll
                for (int nt = 0; nt < 4; nt++) {
                    int rowL = rm + 16*mt + g, rowH = rowL + 8;
                    int colb = kt*128 + cn + 8*nt + 2*tg;
                    *(float2*)(Pout + ((size_t)bh*SEQ + q0 + rowL)*SEQ + colb) = make_float2(0.f, 0.f);
                    *(float2*)(Pout + ((size_t)bh*SEQ + q0 + rowH)*SEQ + colb) = make_float2(0.f, 0.f);
                    int wc = (cn >> 1) + 4*nt + tg;
                    ew[rowL * (EH_STRH/2) + wc] = 0u;
                    ew[rowH * (EH_STRH/2) + wc] = 0u;
                }
        }
        __syncthreads();

        // ---- PV: O[rm..rm+31][dn..dn+15] += E_tile x V_tile ----
        const int ksmax = (kt == ntiles - 1) ? (2*wm + 2) : 8;
        #pragma unroll 2
        for (int ks = 0; ks < ksmax; ks++) {
            uint32_t pa[2][4];
            #pragma unroll
            for (int mt = 0; mt < 2; mt++) {
                int base = (rm + 16*mt + g) * (EH_STRH/2) + 8*ks + tg;
                pa[mt][0] = ew[base];
                pa[mt][1] = ew[base + 8*(EH_STRH/2)];
                pa[mt][2] = ew[base + 4];
                pa[mt][3] = ew[base + 8*(EH_STRH/2) + 4];
            }
            #pragma unroll
            for (int nt = 0; nt < 2; nt++) {
                int bb = (dn + 8*nt + g) * (VT_STRH/2) + 8*ks + tg;
                uint32_t b0 = vw[bb], b1 = vw[bb + 4];
                mma16(o[0][nt], pa[0], b0, b1);
                mma16(o[1][nt], pa[1], b0, b1);
            }
        }
    }
    __syncthreads();   // e-tile dead; scratch overlay safe

    // ---- l / w0 reduce (quad + cross-wn) ----
    #pragma unroll
    for (int s = 0; s < 4; s++) {
        lloc[s] += __shfl_xor_sync(0xffffffffu, lloc[s], 1);
        lloc[s] += __shfl_xor_sync(0xffffffffu, lloc[s], 2);
        w0[s]   += __shfl_xor_sync(0xffffffffu, w0[s], 1);
        w0[s]   += __shfl_xor_sync(0xffffffffu, w0[s], 2);
    }
    if (tg == 0)
        #pragma unroll
        for (int s = 0; s < 4; s++) {
            int row = rm + 16*(s>>1) + 8*(s&1) + g;
            sLR[row*4 + wn] = lloc[s];
            sWR[row*4 + wn] = w0[s];
        }
    __syncthreads();
    float invl[4], w0f[4];
    #pragma unroll
    for (int s = 0; s < 4; s++) {
        int row = rm + 16*(s>>1) + 8*(s&1) + g;
        invl[s] = 1.f / (sLR[row*4] + sLR[row*4+1] + sLR[row*4+2] + sLR[row*4+3]);
        w0f[s]  = (sWR[row*4] + sWR[row*4+1] + sWR[row*4+2] + sWR[row*4+3]) * invl[s];
    }
    if (tg == 0 && wn == 0)
        #pragma unroll
        for (int s = 0; s < 4; s++) {
            int row = rm + 16*(s>>1) + 8*(s&1) + g;
            sINV[row] = invl[s];
        }

    // ---- normalize O ----
    #pragma unroll
    for (int mt = 0; mt < 2; mt++)
        #pragma unroll
        for (int nt = 0; nt < 2; nt++)
            #pragma unroll
            for (int c = 0; c < 4; c++)
                o[mt][nt][c] *= invl[mt*2 + (c>>1)];

    // ---- rel-pos value epilogue: o += sum_j (e_j*invl) * pe_v[j] ----
    #pragma unroll 1
    for (int j = 0; j <= 32; j++) {
        float wj[4];
        #pragma unroll
        for (int s = 0; s < 4; s++) {
            int row = rm + 16*(s>>1) + 8*(s&1) + g;
            wj[s] = (j == 0) ? w0f[s] : sW[row*34 + j] * invl[s];
        }
        #pragma unroll
        for (int nt = 0; nt < 2; nt++) {
            float pe0 = sPEV[j*66 + dn + 8*nt + 2*tg];
            float pe1 = sPEV[j*66 + dn + 8*nt + 2*tg + 1];
            #pragma unroll
            for (int mt = 0; mt < 2; mt++) {
                o[mt][nt][0] = fmaf(wj[mt*2+0], pe0, o[mt][nt][0]);
                o[mt][nt][1] = fmaf(wj[mt*2+0], pe1, o[mt][nt][1]);
                o[mt][nt][2] = fmaf(wj[mt*2+1], pe0, o[mt][nt][2]);
                o[mt][nt][3] = fmaf(wj[mt*2+1], pe1, o[mt][nt][3]);
            }
        }
    }

    // ---- write output ----
    #pragma unroll
    for (int mt = 0; mt < 2; mt++)
        #pragma unroll
        for (int nt = 0; nt < 2; nt++) {
            int rowL = rm + 16*mt + g, rowH = rowL + 8;
            int colb = dn + 8*nt + 2*tg;
            *(float2*)(Out + ((size_t)bh*SEQ + q0 + rowL)*DH + colb) = make_float2(o[mt][nt][0], o[mt][nt][1]);
            *(float2*)(Out + ((size_t)bh*SEQ + q0 + rowH)*DH + colb) = make_float2(o[mt][nt][2], o[mt][nt][3]);
        }

    __syncthreads();   // sINV visible + e-writes to gmem visible block-wide

    // ---- in-place rescale of Pout (e -> p = e/l), L2-hot ----
    {
        const int cols = ntiles * 128;
        for (int r = warp; r < 128; r += 16) {
            float inv = sINV[r];
            float4* rowp = (float4*)(Pout + ((size_t)bh*SEQ + q0 + r)*SEQ);
            for (int c4 = lane; c4 < (cols >> 2); c4 += 32) {
                float4 v = rowp[c4];
                v.x *= inv; v.y *= inv; v.z *= inv; v.w *= inv;
                rowp[c4] = v;
            }
        }
    }

    // ---- zero-fill masked p region ----
    int zc = SEQ - ntiles * 128;
    if (zc > 0) {
        int zq = zc >> 2;
        float4 z = make_float4(0.f, 0.f, 0.f, 0.f);
        float* base = Pout + ((size_t)bh*SEQ + q0)*SEQ + ntiles*128;
        for (int i = tid; i < 128 * zq; i += NTHR) {
            int r = i / zq, c = (i - r * zq) * 4;
            *(float4*)(base + (size_t)r * SEQ + c) = z;
        }
    }
}

extern "C" void kernel_launch(void* const* d_in, const int* in_sizes, int n_in,
                              void* d_out, int out_size)
{
    (void)in_sizes; (void)n_in; (void)out_size;
    const float* Q   = (const float*)d_in[0];
    const float* K   = (const float*)d_in[1];
    const float* V   = (const float*)d_in[2];
    const float* PEK = (const float*)d_in[3];
    const float* PEV = (const float*)d_in[4];
    float* Out  = (float*)d_out;
    float* Pout = Out + (size_t)BH * SEQ * DH;

    knorm_kernel<<<BH, 256>>>(K);
    cudaFuncSetAttribute(relattn_mma, cudaFuncAttributeMaxDynamicSharedMemorySize, SMEM_TOTAL);
    relattn_mma<<<512, NTHR, SMEM_TOTAL>>>(Q, K, V, PEK, PEV, Out, Pout);
}

// round 8
// speedup vs baseline: 1.1913x; 1.0289x over previous
#include <cuda_runtime.h>
#include <cuda_fp16.h>
#include <math.h>
#include <stdint.h>

// B=4,H=16 -> BH=64; S=1024; D=64; rel-pos P=32
#define BH   64
#define SEQ  1024
#define DH   64
#define NTHR 256
#define NROW 64        // q rows per CTA
#define ISD  0.125f
#define NEGINF (-INFINITY)

// strides
#define KH_STRW 36     // K fp16 tile, words per row
#define QH_STRW 36
#define VT_STRW 68     // V^T fp16, words per row
#define EH_STRW 68     // e fp16, words per row
#define QSTG_STR 68    // fp32 Q staging stride (272B, 16B-divisible)

// smem layout (bytes)
#define OFF_KH   0                       // K fp16 [128][72h]    18432
#define OFF_QH   18432                   // Q fp16 [64][72h]      9216
#define OFF_VT   27648                   // V^T fp16 [64][136h]  17408  (preamble overlay: pe_k [33][66] f32)
#define OFF_EH   45056                   // e fp16 [64][136h]    17408  (preamble overlay: Q fp32 [64][68]; tail: reductions)
#define OFF_QPE  62464                   // qpe [64][34] f32      8704
#define OFF_W    71168                   // taps [64][34] f32     8704
#define OFF_PEV  79872                   // pe_v [33][66] f32     8720
#define OFF_M    88592                   // M bound [64]           256
#define SMEM_TOTAL 88848

__device__ float g_maxk[BH];

static __device__ __forceinline__ uint32_t h2u(float a, float b) {
    __half2 h = __floats2half2_rn(a, b);
    return *reinterpret_cast<uint32_t*>(&h);
}
static __device__ __forceinline__ void mma16(float* d, const uint32_t* a,
                                             uint32_t b0, uint32_t b1) {
    asm volatile("mma.sync.aligned.m16n8k16.row.col.f32.f16.f16.f32 "
        "{%0,%1,%2,%3},{%4,%5,%6,%7},{%8,%9},{%0,%1,%2,%3};"
        : "+f"(d[0]), "+f"(d[1]), "+f"(d[2]), "+f"(d[3])
        : "r"(a[0]), "r"(a[1]), "r"(a[2]), "r"(a[3]), "r"(b0), "r"(b1));
}

// ---- precompute: per-bh max ||k_row|| ----
__global__ __launch_bounds__(256, 4)
void knorm_kernel(const float* __restrict__ K)
{
    __shared__ float red[8];
    const int bh = blockIdx.x, tid = threadIdx.x;
    const float* Kb = K + (size_t)bh * SEQ * DH;
    float mx = 0.f;
    for (int r = tid; r < SEQ; r += 256) {
        const float4* kr = (const float4*)(Kb + (size_t)r * DH);
        float s = 0.f;
        #pragma unroll
        for (int i = 0; i < 16; i++) {
            float4 v = kr[i];
            s += v.x*v.x + v.y*v.y + v.z*v.z + v.w*v.w;
        }
        mx = fmaxf(mx, s);
    }
    #pragma unroll
    for (int o = 16; o > 0; o >>= 1) mx = fmaxf(mx, __shfl_xor_sync(0xffffffffu, mx, o));
    if ((tid & 31) == 0) red[tid >> 5] = mx;
    __syncthreads();
    if (tid == 0) {
        float m = red[0];
        #pragma unroll
        for (int i = 1; i < 8; i++) m = fmaxf(m, red[i]);
        g_maxk[bh] = sqrtf(m);
    }
}

__global__ __launch_bounds__(NTHR, 2)
void relattn_mma(const float* __restrict__ Q, const float* __restrict__ K,
                 const float* __restrict__ V, const float* __restrict__ PEK,
                 const float* __restrict__ PEV,
                 float* __restrict__ Out, float* __restrict__ Pout)
{
    extern __shared__ char sm8[];
    uint32_t* kw  = (uint32_t*)(sm8 + OFF_KH);
    uint32_t* qw  = (uint32_t*)(sm8 + OFF_QH);
    uint32_t* vw  = (uint32_t*)(sm8 + OFF_VT);
    uint32_t* ew  = (uint32_t*)(sm8 + OFF_EH);
    float*    qstg= (float*)(sm8 + OFF_EH);      // fp32 Q staging [64][68] (preamble only)
    float*    sPEK= (float*)(sm8 + OFF_VT);      // pe_k overlay (preamble only)
    float*    sQPE= (float*)(sm8 + OFF_QPE);
    float*    sW  = (float*)(sm8 + OFF_W);
    float*    sPEV= (float*)(sm8 + OFF_PEV);
    float*    sM  = (float*)(sm8 + OFF_M);
    // tail reduction scratch overlays e-tile
    float*    sLR = (float*)(sm8 + OFF_EH);            // [64][2]
    float*    sWR = (float*)(sm8 + OFF_EH) + 128;      // [64][2]
    float*    sINV= (float*)(sm8 + OFF_EH) + 256;      // [64]

    const int tid = threadIdx.x, lane = tid & 31, warp = tid >> 5;
    const int g = lane >> 2, tg = lane & 3;
    const int wm = warp & 3, wn = warp >> 2;           // 4 x 2 warp grid
    const int rm = wm * 16, cn = wn * 64, dn = wn * 32;

    // longest CTAs first (qblk descending)
    const int bx = blockIdx.x;
    const int qblk = 15 - (bx >> 6);
    const int bh = bx & 63;
    const int q0 = qblk * NROW;
    const int ntiles = (q0 + NROW + 127) >> 7;
    const int ksmax_diag = (q0 + NROW - (ntiles - 1) * 128) >> 4;   // 4 or 8

    const float* Qb = Q + (size_t)bh * SEQ * DH;
    const float* Kb = K + (size_t)bh * SEQ * DH;
    const float* Vb = V + (size_t)bh * SEQ * DH;
    const float maxk = g_maxk[bh];

    // ---- stage Q (fp32) + pe tables; zero taps ----
    for (int n = 0; n < 4; n++) {
        int i = tid + n * NTHR;
        int r = i >> 4, c = (i & 15) * 4;
        *(float4*)(qstg + r * QSTG_STR + c) =
            *(const float4*)(Qb + (size_t)(q0 + r) * DH + c);
    }
    for (int i = tid; i < 33 * 16; i += NTHR) {
        int r = i >> 4, c = (i & 15) * 4;
        float4 a = *(const float4*)(PEK + r * DH + c);
        sPEK[r*66+c] = a.x; sPEK[r*66+c+1] = a.y; sPEK[r*66+c+2] = a.z; sPEK[r*66+c+3] = a.w;
        float4 b = *(const float4*)(PEV + r * DH + c);
        sPEV[r*66+c] = b.x; sPEV[r*66+c+1] = b.y; sPEV[r*66+c+2] = b.z; sPEV[r*66+c+3] = b.w;
    }
    for (int i = tid; i < NROW * 34; i += NTHR) sW[i] = 0.f;
    __syncthreads();

    // ---- qpe[row][j] = q_row . pe_k[j]  (fp32); 4 threads per row ----
    {
        int row = tid >> 2, quarter = tid & 3;
        const float* qr = qstg + row * QSTG_STR;
        int j0 = quarter * 8, jn = (quarter == 3) ? 9 : 8;
        #pragma unroll 1
        for (int jj = 0; jj < jn; jj++) {
            int j = j0 + jj;
            const float* pk = sPEK + j * 66;
            float a = 0.f;
            #pragma unroll
            for (int d = 0; d < 64; d++) a = fmaf(qr[d], pk[d], a);
            sQPE[row * 34 + j] = a;
        }
    }
    __syncthreads();

    // ---- M bound per row + build Q fp16 tile ----
    if (tid < NROW) {
        const float* qr = qstg + tid * QSTG_STR;
        float qn = 0.f;
        #pragma unroll
        for (int d = 0; d < 64; d++) qn = fmaf(qr[d], qr[d], qn);
        float mb = sQPE[tid * 34];
        #pragma unroll
        for (int j = 1; j < 33; j++) mb = fmaxf(mb, sQPE[tid * 34 + j]);
        sM[tid] = sqrtf(qn) * maxk + mb;
    }
    for (int n = 0; n < 4; n++) {
        int i = tid + n * NTHR;
        int r = i >> 4, c = (i & 15) * 4;
        const float* s = qstg + r * QSTG_STR + c;
        uint2 u; u.x = h2u(s[0], s[1]); u.y = h2u(s[2], s[3]);
        *(uint2*)(qw + r * QH_STRW + c/2) = u;
    }
    __syncthreads();

    float Mrow[2];
    #pragma unroll
    for (int s = 0; s < 2; s++) Mrow[s] = sM[rm + 8*s + g];

    // ================= single pass: QK -> e -> emit + PV =================
    float lloc[2] = {0.f, 0.f};
    float w0[2]   = {0.f, 0.f};
    float o[4][4] = {};

    for (int kt = 0; kt < ntiles; kt++) {
        const float* Kt = Kb + (size_t)kt * 128 * DH;
        const float* Vt = Vb + (size_t)kt * 128 * DH;

        // prefetch K/V (overlaps previous tile's PV and the barrier)
        float4 kreg[8], vreg[8];
        #pragma unroll
        for (int n = 0; n < 8; n++) {
            int i = tid + n * NTHR;
            int r = i >> 4, c = (i & 15) * 4;
            kreg[n] = *(const float4*)(Kt + (size_t)r * DH + c);
        }
        #pragma unroll
        for (int n = 0; n < 2; n++) {
            int idx = tid + n * NTHR;
            int vkp = idx & 63, vdb = (idx >> 6) * 8;
            vreg[4*n+0] = *(const float4*)(Vt + (size_t)(2*vkp)   * DH + vdb);
            vreg[4*n+1] = *(const float4*)(Vt + (size_t)(2*vkp)   * DH + vdb + 4);
            vreg[4*n+2] = *(const float4*)(Vt + (size_t)(2*vkp+1) * DH + vdb);
            vreg[4*n+3] = *(const float4*)(Vt + (size_t)(2*vkp+1) * DH + vdb + 4);
        }
        __syncthreads();
        #pragma unroll
        for (int n = 0; n < 8; n++) {
            int i = tid + n * NTHR;
            int r = i >> 4, c = (i & 15) * 4;
            uint2 u; u.x = h2u(kreg[n].x, kreg[n].y); u.y = h2u(kreg[n].z, kreg[n].w);
            *(uint2*)(kw + r * KH_STRW + c/2) = u;
        }
        #pragma unroll
        for (int n = 0; n < 2; n++) {
            int idx = tid + n * NTHR;
            int vkp = idx & 63, vdb = (idx >> 6) * 8;
            const float* v0 = (const float*)&vreg[4*n];
            const float* v1 = (const float*)&vreg[4*n+2];
            #pragma unroll
            for (int j = 0; j < 8; j++)
                vw[(vdb + j) * VT_STRW + vkp] = h2u(v0[j], v1[j]);
        }
        __syncthreads();

        const bool live = (kt*128 + cn) <= (q0 + rm + 15);

        // ---- score MMAs: 16 rows x 64 cols per warp ----
        float acc[8][4] = {};
        if (live) {
            #pragma unroll
            for (int ks = 0; ks < 4; ks++) {
                uint32_t qa[4];
                int base = (rm + g) * QH_STRW + 8*ks + tg;
                qa[0] = qw[base];
                qa[1] = qw[base + 8*QH_STRW];
                qa[2] = qw[base + 4];
                qa[3] = qw[base + 8*QH_STRW + 4];
                #pragma unroll
                for (int nt = 0; nt < 8; nt++) {
                    int bb = (cn + 8*nt + g) * KH_STRW + 8*ks + tg;
                    mma16(acc[nt], qa, kw[bb], kw[bb + 4]);
                }
            }
        }

        // ---- bias + mask + e; emit e; l/w0/taps ----
        if (live) {
            #pragma unroll
            for (int nt = 0; nt < 8; nt++) {
                float p[4];
                #pragma unroll
                for (int c = 0; c < 4; c++) {
                    int s = c >> 1;
                    int row = rm + 8*s + g;
                    int col = kt*128 + cn + 8*nt + 2*tg + (c&1);
                    int qg = q0 + row;
                    float v = NEGINF;
                    if (col <= qg) {
                        int j = col - qg + 32; j = j < 0 ? 0 : j;
                        v = acc[nt][c] + sQPE[row*34 + j];
                    }
                    float e = __expf((v - Mrow[s]) * ISD);
                    p[c] = e;
                    lloc[s] += e;
                    if (col <= qg - 32) w0[s] += e;
                    else if (col <= qg) sW[row*34 + (col - qg + 32)] = e;
                }
                int rowL = rm + g, rowH = rm + 8 + g;
                int colb = kt*128 + cn + 8*nt + 2*tg;
                *(float2*)(Pout + ((size_t)bh*SEQ + q0 + rowL)*SEQ + colb) = make_float2(p[0], p[1]);
                *(float2*)(Pout + ((size_t)bh*SEQ + q0 + rowH)*SEQ + colb) = make_float2(p[2], p[3]);
                int wc = (cn >> 1) + 4*nt + tg;
                ew[rowL * EH_STRW + wc] = h2u(p[0], p[1]);
                ew[rowH * EH_STRW + wc] = h2u(p[2], p[3]);
            }
        } else {
            #pragma unroll
            for (int nt = 0; nt < 8; nt++) {
                int rowL = rm + g, rowH = rm + 8 + g;
                int colb = kt*128 + cn + 8*nt + 2*tg;
                *(float2*)(Pout + ((size_t)bh*SEQ + q0 + rowL)*SEQ + colb) = make_float2(0.f, 0.f);
                *(float2*)(Pout + ((size_t)bh*SEQ + q0 + rowH)*SEQ + colb) = make_float2(0.f, 0.f);
                int wc = (cn >> 1) + 4*nt + tg;
                ew[rowL * EH_STRW + wc] = 0u;
                ew[rowH * EH_STRW + wc] = 0u;
            }
        }
        __syncthreads();

        // ---- PV: O[rm..rm+15][dn..dn+31] += E_tile x V_tile ----
        const int ksmax = (kt == ntiles - 1) ? ksmax_diag : 8;
        #pragma unroll 2
        for (int ks = 0; ks < ksmax; ks++) {
            uint32_t pa[4];
            int base = (rm + g) * EH_STRW + 8*ks + tg;
            pa[0] = ew[base];
            pa[1] = ew[base + 8*EH_STRW];
            pa[2] = ew[base + 4];
            pa[3] = ew[base + 8*EH_STRW + 4];
            #pragma unroll
            for (int nt = 0; nt < 4; nt++) {
                int bb = (dn + 8*nt + g) * VT_STRW + 8*ks + tg;
                mma16(o[nt], pa, vw[bb], vw[bb + 4]);
            }
        }
    }
    __syncthreads();   // e-tile dead; scratch overlay safe

    // ---- l / w0 reduce (quad + cross-wn) ----
    #pragma unroll
    for (int s = 0; s < 2; s++) {
        lloc[s] += __shfl_xor_sync(0xffffffffu, lloc[s], 1);
        lloc[s] += __shfl_xor_sync(0xffffffffu, lloc[s], 2);
        w0[s]   += __shfl_xor_sync(0xffffffffu, w0[s], 1);
        w0[s]   += __shfl_xor_sync(0xffffffffu, w0[s], 2);
    }
    if (tg == 0)
        #pragma unroll
        for (int s = 0; s < 2; s++) {
            int row = rm + 8*s + g;
            sLR[row*2 + wn] = lloc[s];
            sWR[row*2 + wn] = w0[s];
        }
    __syncthreads();
    float invl[2], w0f[2];
    #pragma unroll
    for (int s = 0; s < 2; s++) {
        int row = rm + 8*s + g;
        invl[s] = 1.f / (sLR[row*2] + sLR[row*2+1]);
        w0f[s]  = (sWR[row*2] + sWR[row*2+1]) * invl[s];
    }
    if (tg == 0 && wn == 0)
        #pragma unroll
        for (int s = 0; s < 2; s++) sINV[rm + 8*s + g] = invl[s];

    // ---- normalize O ----
    #pragma unroll
    for (int nt = 0; nt < 4; nt++)
        #pragma unroll
        for (int c = 0; c < 4; c++)
            o[nt][c] *= invl[c>>1];

    // ---- rel-pos value epilogue ----
    #pragma unroll 1
    for (int j = 0; j <= 32; j++) {
        float wj[2];
        #pragma unroll
        for (int s = 0; s < 2; s++) {
            int row = rm + 8*s + g;
            wj[s] = (j == 0) ? w0f[s] : sW[row*34 + j] * invl[s];
        }
        #pragma unroll
        for (int nt = 0; nt < 4; nt++) {
            float pe0 = sPEV[j*66 + dn + 8*nt + 2*tg];
            float pe1 = sPEV[j*66 + dn + 8*nt + 2*tg + 1];
            o[nt][0] = fmaf(wj[0], pe0, o[nt][0]);
            o[nt][1] = fmaf(wj[0], pe1, o[nt][1]);
            o[nt][2] = fmaf(wj[1], pe0, o[nt][2]);
            o[nt][3] = fmaf(wj[1], pe1, o[nt][3]);
        }
    }

    // ---- write output ----
    #pragma unroll
    for (int nt = 0; nt < 4; nt++) {
        int rowL = rm + g, rowH = rm + 8 + g;
        int colb = dn + 8*nt + 2*tg;
        *(float2*)(Out + ((size_t)bh*SEQ + q0 + rowL)*DH + colb) = make_float2(o[nt][0], o[nt][1]);
        *(float2*)(Out + ((size_t)bh*SEQ + q0 + rowH)*DH + colb) = make_float2(o[nt][2], o[nt][3]);
    }

    __syncthreads();   // sINV visible + e-writes to gmem visible block-wide

    // ---- in-place rescale of Pout (e -> p = e/l), L2-hot ----
    {
        const int cols = ntiles * 128;
        for (int r = warp; r < NROW; r += 8) {
            float inv = sINV[r];
            float4* rowp = (float4*)(Pout + ((size_t)bh*SEQ + q0 + r)*SEQ);
            for (int c4 = lane; c4 < (cols >> 2); c4 += 32) {
                float4 v = rowp[c4];
                v.x *= inv; v.y *= inv; v.z *= inv; v.w *= inv;
                rowp[c4] = v;
            }
        }
    }

    // ---- zero-fill masked p region ----
    int zc = SEQ - ntiles * 128;
    if (zc > 0) {
        int zq = zc >> 2;
        float4 z = make_float4(0.f, 0.f, 0.f, 0.f);
        float* base = Pout + ((size_t)bh*SEQ + q0)*SEQ + ntiles*128;
        for (int i = tid; i < NROW * zq; i += NTHR) {
            int r = i / zq, c = (i - r * zq) * 4;
            *(float4*)(base + (size_t)r * SEQ + c) = z;
        }
    }
}

extern "C" void kernel_launch(void* const* d_in, const int* in_sizes, int n_in,
                              void* d_out, int out_size)
{
    (void)in_sizes; (void)n_in; (void)out_size;
    const float* Q   = (const float*)d_in[0];
    const float* K   = (const float*)d_in[1];
    const float* V   = (const float*)d_in[2];
    const float* PEK = (const float*)d_in[3];
    const float* PEV = (const float*)d_in[4];
    float* Out  = (float*)d_out;
    float* Pout = Out + (size_t)BH * SEQ * DH;

    knorm_kernel<<<BH, 256>>>(K);
    cudaFuncSetAttribute(relattn_mma, cudaFuncAttributeMaxDynamicSharedMemorySize, SMEM_TOTAL);
    relattn_mma<<<1024, NTHR, SMEM_TOTAL>>>(Q, K, V, PEK, PEV, Out, Pout);
}